// round 4
// baseline (speedup 1.0000x reference)
#include <cuda_runtime.h>

#define NN 50000
#define EE 800000
#define DD 128

// ---------------- device-global scratch (no allocations allowed) ------------
__device__ float d_g[NN * DD];      // g = relu(X@W1+b1) @ (W2@Wout) + (b2@Wout)
__device__ float d_Wc[DD * DD];     // folded W2 @ Wout
__device__ float d_bc[DD];          // folded b2 @ Wout
__device__ int   d_deg[NN];
__device__ int   d_offs[NN + 1];
__device__ int   d_cursor[NN];
__device__ int   d_csr[EE];
__device__ int   d_is64;            // 1 if edge_index is int64, 0 if int32

// ---------------- edge_index dtype handling --------------------------------
// JAX may emit int32 (x64 disabled, the default) or int64 for edge_index.
// For int64 little-endian values < 2^31, odd int32 words are all zero;
// for int32 node ids, 16 consecutive odd words all-zero is ~impossible.
__global__ void k_detect(const int* __restrict__ ei32) {
    if (threadIdx.x == 0) {
        int s = 0;
        #pragma unroll
        for (int i = 0; i < 16; i++) s |= ei32[2 * i + 1];
        d_is64 = (s == 0) ? 1 : 0;
    }
}

__device__ __forceinline__ int edge_at(const void* ei, int is64, int idx) {
    if (is64) return (int)((const long long*)ei)[idx];
    return ((const int*)ei)[idx];
}

// ---------------- tiny kernels ---------------------------------------------
__global__ void k_zero_deg() {
    int i = blockIdx.x * blockDim.x + threadIdx.x;
    if (i < NN) d_deg[i] = 0;
}

__global__ void k_count(const void* __restrict__ ei) {
    int i = blockIdx.x * blockDim.x + threadIdx.x;
    if (i < EE) {
        int is64 = d_is64;
        int dst = edge_at(ei, is64, EE + i);
        atomicAdd(&d_deg[dst], 1);
    }
}

// single-block exclusive scan over d_deg -> d_offs / d_cursor
__global__ void k_scan() {
    const int T = 1024;
    const int CH = (NN + T - 1) / T;  // 49
    int tid = threadIdx.x;
    int lane = tid & 31, wid = tid >> 5;
    int s0 = tid * CH;
    int s1 = s0 + CH; if (s1 > NN) s1 = NN;
    if (s0 > NN) s0 = NN;

    int sum = 0;
    for (int i = s0; i < s1; i++) sum += d_deg[i];

    // warp inclusive scan of per-thread sums
    int inc = sum;
    #pragma unroll
    for (int off = 1; off < 32; off <<= 1) {
        int t = __shfl_up_sync(0xffffffffu, inc, off);
        if (lane >= off) inc += t;
    }
    __shared__ int wsum[32];
    if (lane == 31) wsum[wid] = inc;
    __syncthreads();
    if (wid == 0) {
        int v = wsum[lane];
        #pragma unroll
        for (int off = 1; off < 32; off <<= 1) {
            int t = __shfl_up_sync(0xffffffffu, v, off);
            if (lane >= off) v += t;
        }
        wsum[lane] = v;
    }
    __syncthreads();
    int prefix = (inc - sum) + (wid ? wsum[wid - 1] : 0);

    int run = prefix;
    for (int i = s0; i < s1; i++) {
        d_offs[i] = run;
        d_cursor[i] = run;
        run += d_deg[i];
    }
    if (tid == 0) d_offs[NN] = wsum[31];
}

__global__ void k_fill(const void* __restrict__ ei) {
    int i = blockIdx.x * blockDim.x + threadIdx.x;
    if (i < EE) {
        int is64 = d_is64;
        int src = edge_at(ei, is64, i);
        int dst = edge_at(ei, is64, EE + i);
        int p = atomicAdd(&d_cursor[dst], 1);
        d_csr[p] = src;
    }
}

// fold W2 @ Wout -> d_Wc ; b2 @ Wout -> d_bc
__global__ void k_pre(const float* __restrict__ w2, const float* __restrict__ wo,
                      const float* __restrict__ b2) {
    int j = threadIdx.x;  // 0..127
    if (blockIdx.x < DD) {
        int i = blockIdx.x;
        float acc = 0.f;
        #pragma unroll 8
        for (int k = 0; k < DD; k++) acc += w2[i * DD + k] * wo[k * DD + j];
        d_Wc[i * DD + j] = acc;
    } else {
        float acc = 0.f;
        #pragma unroll 8
        for (int k = 0; k < DD; k++) acc += b2[k] * wo[k * DD + j];
        d_bc[j] = acc;
    }
}

// ---------------- fused 2-GEMM edge MLP (rows 0..NN-1 only) ----------------
// g = relu(X @ W1 + b1) @ Wc + bc     (all [*,128] x [128,128])
// BM=64 rows/block, 256 threads as 16x16, TM=4 x TN=8 per thread, BK=16.
__global__ __launch_bounds__(256) void k_mlp(const float* __restrict__ X,
                                             const float* __restrict__ W1,
                                             const float* __restrict__ b1) {
    __shared__ float Xs[64][132];   // padded, float4-aligned columns
    __shared__ float Ws[16][128];

    int tid = threadIdx.x;
    int tx = tid & 15;        // column group: cols tx*8 .. tx*8+7
    int ty = tid >> 4;        // row group:    rows ty*4 .. ty*4+3
    int m0 = blockIdx.x * 64;

    // load X tile [64,128] (zero-pad out-of-range rows)
    #pragma unroll
    for (int r = 0; r < 8; r++) {
        int f = tid + 256 * r;          // float4 index, 0..2047
        int row = f >> 5;               // 32 float4 per row
        int col = (f & 31) << 2;
        float4 v = make_float4(0.f, 0.f, 0.f, 0.f);
        if (m0 + row < NN)
            v = *reinterpret_cast<const float4*>(&X[(size_t)(m0 + row) * DD + col]);
        *reinterpret_cast<float4*>(&Xs[row][col]) = v;
    }

    float bias1[8], bcr[8];
    #pragma unroll
    for (int j = 0; j < 8; j++) {
        bias1[j] = b1[tx * 8 + j];
        bcr[j]   = d_bc[tx * 8 + j];
    }

    float C[4][8];

    #pragma unroll 1
    for (int phase = 0; phase < 2; phase++) {
        const float* W = (phase == 0) ? W1 : d_Wc;
        #pragma unroll
        for (int i = 0; i < 4; i++)
            #pragma unroll
            for (int j = 0; j < 8; j++) C[i][j] = 0.f;

        for (int k0 = 0; k0 < DD; k0 += 16) {
            __syncthreads();  // Ws reuse + Xs visibility
            // load Ws[16][128]: 2048 floats, 8 per thread
            {
                const float* wp = W + k0 * DD;
                float4 v0 = *reinterpret_cast<const float4*>(&wp[tid * 8]);
                float4 v1 = *reinterpret_cast<const float4*>(&wp[tid * 8 + 4]);
                *reinterpret_cast<float4*>(&Ws[0][0] + tid * 8)     = v0;
                *reinterpret_cast<float4*>(&Ws[0][0] + tid * 8 + 4) = v1;
            }
            __syncthreads();
            #pragma unroll
            for (int k = 0; k < 16; k++) {
                float a[4], b[8];
                #pragma unroll
                for (int i = 0; i < 4; i++) a[i] = Xs[ty * 4 + i][k0 + k];
                float4 bv0 = *reinterpret_cast<float4*>(&Ws[k][tx * 8]);
                float4 bv1 = *reinterpret_cast<float4*>(&Ws[k][tx * 8 + 4]);
                b[0] = bv0.x; b[1] = bv0.y; b[2] = bv0.z; b[3] = bv0.w;
                b[4] = bv1.x; b[5] = bv1.y; b[6] = bv1.z; b[7] = bv1.w;
                #pragma unroll
                for (int i = 0; i < 4; i++)
                    #pragma unroll
                    for (int j = 0; j < 8; j++) C[i][j] += a[i] * b[j];
            }
        }

        if (phase == 0) {
            __syncthreads();  // everyone done reading Xs
            #pragma unroll
            for (int i = 0; i < 4; i++)
                #pragma unroll
                for (int j = 0; j < 8; j++) {
                    float v = C[i][j] + bias1[j];
                    Xs[ty * 4 + i][tx * 8 + j] = v > 0.f ? v : 0.f;
                }
            // next phase's first __syncthreads() makes these visible
        } else {
            #pragma unroll
            for (int i = 0; i < 4; i++) {
                int row = m0 + ty * 4 + i;
                if (row < NN) {
                    float4 o0 = make_float4(C[i][0] + bcr[0], C[i][1] + bcr[1],
                                            C[i][2] + bcr[2], C[i][3] + bcr[3]);
                    float4 o1 = make_float4(C[i][4] + bcr[4], C[i][5] + bcr[5],
                                            C[i][6] + bcr[6], C[i][7] + bcr[7]);
                    *reinterpret_cast<float4*>(&d_g[(size_t)row * DD + tx * 8])     = o0;
                    *reinterpret_cast<float4*>(&d_g[(size_t)row * DD + tx * 8 + 4]) = o1;
                }
            }
        }
    }
}

// ---------------- per-node gather + mean + bias -----------------------------
// one warp per node; lane handles a float4 chunk (128 floats / 32 lanes)
__global__ __launch_bounds__(256) void k_gather(const float* __restrict__ bo,
                                                float* __restrict__ out) {
    int gtid = blockIdx.x * blockDim.x + threadIdx.x;
    int node = gtid >> 5;
    int lane = gtid & 31;
    if (node >= NN) return;

    const float4* g4 = reinterpret_cast<const float4*>(d_g);
    float4 acc = g4[(size_t)node * 32 + lane];  // self-loop contribution h[node]

    int start = d_offs[node];
    int end   = d_offs[node + 1];

    for (int j = start; j < end; j += 32) {
        int v = (j + lane < end) ? d_csr[j + lane] : 0;
        int cnt = end - j; if (cnt > 32) cnt = 32;
        for (int i = 0; i < cnt; i++) {
            int s = __shfl_sync(0xffffffffu, v, i);
            float4 t = g4[(size_t)s * 32 + lane];
            acc.x += t.x; acc.y += t.y; acc.z += t.z; acc.w += t.w;
        }
    }

    float inv = 1.0f / (float)(end - start + 1);
    float4 bb = reinterpret_cast<const float4*>(bo)[lane];
    float4 o = make_float4(acc.x * inv + bb.x, acc.y * inv + bb.y,
                           acc.z * inv + bb.z, acc.w * inv + bb.w);
    reinterpret_cast<float4*>(out)[(size_t)node * 32 + lane] = o;
}

// ---------------- launch ----------------------------------------------------
extern "C" void kernel_launch(void* const* d_in, const int* in_sizes, int n_in,
                              void* d_out, int out_size) {
    const void* ei       = d_in[0];                     // edge_index [2, EE] int32 or int64
    const float* eattr   = (const float*)d_in[1];       // edge_attr [EE, 128]
    const float* w2_1    = (const float*)d_in[8];
    const float* b2_1    = (const float*)d_in[9];
    const float* w2_2    = (const float*)d_in[10];
    const float* b2_2    = (const float*)d_in[11];
    const float* w2_out  = (const float*)d_in[12];
    const float* b2_out  = (const float*)d_in[13];
    float* out = (float*)d_out;

    k_detect<<<1, 32>>>((const int*)ei);
    k_zero_deg<<<(NN + 255) / 256, 256>>>();
    k_count<<<(EE + 255) / 256, 256>>>(ei);
    k_scan<<<1, 1024>>>();
    k_fill<<<(EE + 255) / 256, 256>>>(ei);
    k_pre<<<DD + 1, DD>>>(w2_2, w2_out, b2_2);
    k_mlp<<<(NN + 63) / 64, 256>>>(eattr, w2_1, b2_1);
    k_gather<<<(NN * 32 + 255) / 256, 256>>>(b2_out, out);
}

// round 5
// speedup vs baseline: 1.3437x; 1.3437x over previous
#include <cuda_runtime.h>

#define NN 50000
#define EE 800000
#define DD 128
#define SCAN_G ((NN + 255) / 256)   // 196 blocks

// ---------------- device-global scratch (no allocations allowed) ------------
__device__ float d_g[NN * DD];      // g = relu(X@W1+b1) @ (W2@Wout) + (b2@Wout)
__device__ float d_Wc[DD * DD];     // folded W2 @ Wout
__device__ float d_bc[DD];          // folded b2 @ Wout
__device__ int   d_deg[NN];
__device__ int   d_offs[NN + 1];
__device__ int   d_cursor[NN];
__device__ int   d_csr[EE];
__device__ int   d_is64;            // 1 if edge_index is int64, 0 if int32
__device__ int   d_bsum[SCAN_G];
__device__ int   d_boff[SCAN_G];

// ---------------- edge_index dtype handling --------------------------------
// JAX may emit int32 (x64 disabled, the default) or int64 for edge_index.
// For int64 little-endian values < 2^31, odd int32 words are all zero;
// for int32 node ids, 16 consecutive odd words all-zero is ~impossible.
__global__ void k_detect(const int* __restrict__ ei32) {
    if (threadIdx.x == 0) {
        int s = 0;
        #pragma unroll
        for (int i = 0; i < 16; i++) s |= ei32[2 * i + 1];
        d_is64 = (s == 0) ? 1 : 0;
    }
}

__device__ __forceinline__ int edge_at(const void* ei, int is64, int idx) {
    if (is64) return (int)((const long long*)ei)[idx];
    return ((const int*)ei)[idx];
}

// ---------------- tiny kernels ---------------------------------------------
__global__ void k_zero_deg() {
    int i = blockIdx.x * blockDim.x + threadIdx.x;
    if (i < NN) d_deg[i] = 0;
}

__global__ void k_count(const void* __restrict__ ei) {
    int i = blockIdx.x * blockDim.x + threadIdx.x;
    if (i < EE) {
        int is64 = d_is64;
        int dst = edge_at(ei, is64, EE + i);
        atomicAdd(&d_deg[dst], 1);
    }
}

// ---------------- hierarchical exclusive scan over d_deg --------------------
// Stage 1: per-block (256 elems) exclusive scan -> d_offs (local), totals -> d_bsum
__global__ __launch_bounds__(256) void k_scan_blk() {
    __shared__ int ws[8];
    int tid = threadIdx.x;
    int i = blockIdx.x * 256 + tid;
    int lane = tid & 31, wid = tid >> 5;

    int v = (i < NN) ? d_deg[i] : 0;

    int inc = v;
    #pragma unroll
    for (int o = 1; o < 32; o <<= 1) {
        int t = __shfl_up_sync(0xffffffffu, inc, o);
        if (lane >= o) inc += t;
    }
    if (lane == 31) ws[wid] = inc;
    __syncthreads();
    if (wid == 0 && lane < 8) {
        int t = ws[lane];
        #pragma unroll
        for (int o = 1; o < 8; o <<= 1) {
            int u = __shfl_up_sync(0x000000ffu, t, o);
            if (lane >= o) t += u;
        }
        ws[lane] = t;
    }
    __syncthreads();
    int excl = inc - v + (wid ? ws[wid - 1] : 0);
    if (i < NN) d_offs[i] = excl;
    if (tid == 255) d_bsum[blockIdx.x] = ws[7];
}

// Stage 2: scan the SCAN_G block totals (single small block)
__global__ __launch_bounds__(256) void k_scan_top() {
    __shared__ int ws[8];
    int tid = threadIdx.x;
    int lane = tid & 31, wid = tid >> 5;

    int v = (tid < SCAN_G) ? d_bsum[tid] : 0;

    int inc = v;
    #pragma unroll
    for (int o = 1; o < 32; o <<= 1) {
        int t = __shfl_up_sync(0xffffffffu, inc, o);
        if (lane >= o) inc += t;
    }
    if (lane == 31) ws[wid] = inc;
    __syncthreads();
    if (wid == 0 && lane < 8) {
        int t = ws[lane];
        #pragma unroll
        for (int o = 1; o < 8; o <<= 1) {
            int u = __shfl_up_sync(0x000000ffu, t, o);
            if (lane >= o) t += u;
        }
        ws[lane] = t;
    }
    __syncthreads();
    int excl = inc - v + (wid ? ws[wid - 1] : 0);
    if (tid < SCAN_G) d_boff[tid] = excl;
    if (tid == 255) d_offs[NN] = ws[7];   // grand total (== EE)
}

// Stage 3: add block offsets, produce final d_offs + d_cursor
__global__ __launch_bounds__(256) void k_scan_add() {
    int i = blockIdx.x * 256 + threadIdx.x;
    if (i < NN) {
        int o = d_offs[i] + d_boff[blockIdx.x];
        d_offs[i] = o;
        d_cursor[i] = o;
    }
}

__global__ void k_fill(const void* __restrict__ ei) {
    int i = blockIdx.x * blockDim.x + threadIdx.x;
    if (i < EE) {
        int is64 = d_is64;
        int src = edge_at(ei, is64, i);
        int dst = edge_at(ei, is64, EE + i);
        int p = atomicAdd(&d_cursor[dst], 1);
        d_csr[p] = src;
    }
}

// fold W2 @ Wout -> d_Wc ; b2 @ Wout -> d_bc
__global__ void k_pre(const float* __restrict__ w2, const float* __restrict__ wo,
                      const float* __restrict__ b2) {
    int j = threadIdx.x;  // 0..127
    if (blockIdx.x < DD) {
        int i = blockIdx.x;
        float acc = 0.f;
        #pragma unroll 8
        for (int k = 0; k < DD; k++) acc += w2[i * DD + k] * wo[k * DD + j];
        d_Wc[i * DD + j] = acc;
    } else {
        float acc = 0.f;
        #pragma unroll 8
        for (int k = 0; k < DD; k++) acc += b2[k] * wo[k * DD + j];
        d_bc[j] = acc;
    }
}

// ---------------- fused 2-GEMM edge MLP (rows 0..NN-1 only) ----------------
// g = relu(X @ W1 + b1) @ Wc + bc     (all [*,128] x [128,128])
// BM=64 rows/block, 256 threads as 16x16, TM=4 x TN=8 per thread, BK=16.
__global__ __launch_bounds__(256) void k_mlp(const float* __restrict__ X,
                                             const float* __restrict__ W1,
                                             const float* __restrict__ b1) {
    __shared__ float Xs[64][132];   // padded, float4-aligned columns
    __shared__ float Ws[16][128];

    int tid = threadIdx.x;
    int tx = tid & 15;        // column group: cols tx*8 .. tx*8+7
    int ty = tid >> 4;        // row group:    rows ty*4 .. ty*4+3
    int m0 = blockIdx.x * 64;

    // load X tile [64,128] (zero-pad out-of-range rows)
    #pragma unroll
    for (int r = 0; r < 8; r++) {
        int f = tid + 256 * r;          // float4 index, 0..2047
        int row = f >> 5;               // 32 float4 per row
        int col = (f & 31) << 2;
        float4 v = make_float4(0.f, 0.f, 0.f, 0.f);
        if (m0 + row < NN)
            v = *reinterpret_cast<const float4*>(&X[(size_t)(m0 + row) * DD + col]);
        *reinterpret_cast<float4*>(&Xs[row][col]) = v;
    }

    float bias1[8], bcr[8];
    #pragma unroll
    for (int j = 0; j < 8; j++) {
        bias1[j] = b1[tx * 8 + j];
        bcr[j]   = d_bc[tx * 8 + j];
    }

    float C[4][8];

    #pragma unroll 1
    for (int phase = 0; phase < 2; phase++) {
        const float* W = (phase == 0) ? W1 : d_Wc;
        #pragma unroll
        for (int i = 0; i < 4; i++)
            #pragma unroll
            for (int j = 0; j < 8; j++) C[i][j] = 0.f;

        for (int k0 = 0; k0 < DD; k0 += 16) {
            __syncthreads();  // Ws reuse + Xs visibility
            // load Ws[16][128]: 2048 floats, 8 per thread
            {
                const float* wp = W + k0 * DD;
                float4 v0 = *reinterpret_cast<const float4*>(&wp[tid * 8]);
                float4 v1 = *reinterpret_cast<const float4*>(&wp[tid * 8 + 4]);
                *reinterpret_cast<float4*>(&Ws[0][0] + tid * 8)     = v0;
                *reinterpret_cast<float4*>(&Ws[0][0] + tid * 8 + 4) = v1;
            }
            __syncthreads();
            #pragma unroll
            for (int k = 0; k < 16; k++) {
                float a[4], b[8];
                #pragma unroll
                for (int i = 0; i < 4; i++) a[i] = Xs[ty * 4 + i][k0 + k];
                float4 bv0 = *reinterpret_cast<float4*>(&Ws[k][tx * 8]);
                float4 bv1 = *reinterpret_cast<float4*>(&Ws[k][tx * 8 + 4]);
                b[0] = bv0.x; b[1] = bv0.y; b[2] = bv0.z; b[3] = bv0.w;
                b[4] = bv1.x; b[5] = bv1.y; b[6] = bv1.z; b[7] = bv1.w;
                #pragma unroll
                for (int i = 0; i < 4; i++)
                    #pragma unroll
                    for (int j = 0; j < 8; j++) C[i][j] += a[i] * b[j];
            }
        }

        if (phase == 0) {
            __syncthreads();  // everyone done reading Xs
            #pragma unroll
            for (int i = 0; i < 4; i++)
                #pragma unroll
                for (int j = 0; j < 8; j++) {
                    float v = C[i][j] + bias1[j];
                    Xs[ty * 4 + i][tx * 8 + j] = v > 0.f ? v : 0.f;
                }
            // next phase's first __syncthreads() makes these visible
        } else {
            #pragma unroll
            for (int i = 0; i < 4; i++) {
                int row = m0 + ty * 4 + i;
                if (row < NN) {
                    float4 o0 = make_float4(C[i][0] + bcr[0], C[i][1] + bcr[1],
                                            C[i][2] + bcr[2], C[i][3] + bcr[3]);
                    float4 o1 = make_float4(C[i][4] + bcr[4], C[i][5] + bcr[5],
                                            C[i][6] + bcr[6], C[i][7] + bcr[7]);
                    *reinterpret_cast<float4*>(&d_g[(size_t)row * DD + tx * 8])     = o0;
                    *reinterpret_cast<float4*>(&d_g[(size_t)row * DD + tx * 8 + 4]) = o1;
                }
            }
        }
    }
}

// ---------------- per-node gather + mean + bias -----------------------------
// one warp per node; lane handles a float4 chunk (128 floats / 32 lanes)
__global__ __launch_bounds__(256) void k_gather(const float* __restrict__ bo,
                                                float* __restrict__ out) {
    int gtid = blockIdx.x * blockDim.x + threadIdx.x;
    int node = gtid >> 5;
    int lane = gtid & 31;
    if (node >= NN) return;

    const float4* g4 = reinterpret_cast<const float4*>(d_g);
    float4 acc = g4[(size_t)node * 32 + lane];  // self-loop contribution h[node]

    int start = d_offs[node];
    int end   = d_offs[node + 1];

    for (int j = start; j < end; j += 32) {
        int v = (j + lane < end) ? d_csr[j + lane] : 0;
        int cnt = end - j; if (cnt > 32) cnt = 32;
        for (int i = 0; i < cnt; i++) {
            int s = __shfl_sync(0xffffffffu, v, i);
            float4 t = g4[(size_t)s * 32 + lane];
            acc.x += t.x; acc.y += t.y; acc.z += t.z; acc.w += t.w;
        }
    }

    float inv = 1.0f / (float)(end - start + 1);
    float4 bb = reinterpret_cast<const float4*>(bo)[lane];
    float4 o = make_float4(acc.x * inv + bb.x, acc.y * inv + bb.y,
                           acc.z * inv + bb.z, acc.w * inv + bb.w);
    reinterpret_cast<float4*>(out)[(size_t)node * 32 + lane] = o;
}

// ---------------- launch ----------------------------------------------------
extern "C" void kernel_launch(void* const* d_in, const int* in_sizes, int n_in,
                              void* d_out, int out_size) {
    const void* ei       = d_in[0];                     // edge_index [2, EE] int32 or int64
    const float* eattr   = (const float*)d_in[1];       // edge_attr [EE, 128]
    const float* w2_1    = (const float*)d_in[8];
    const float* b2_1    = (const float*)d_in[9];
    const float* w2_2    = (const float*)d_in[10];
    const float* b2_2    = (const float*)d_in[11];
    const float* w2_out  = (const float*)d_in[12];
    const float* b2_out  = (const float*)d_in[13];
    float* out = (float*)d_out;

    k_detect<<<1, 32>>>((const int*)ei);
    k_zero_deg<<<(NN + 255) / 256, 256>>>();
    k_count<<<(EE + 255) / 256, 256>>>(ei);
    k_scan_blk<<<SCAN_G, 256>>>();
    k_scan_top<<<1, 256>>>();
    k_scan_add<<<SCAN_G, 256>>>();
    k_fill<<<(EE + 255) / 256, 256>>>(ei);
    k_pre<<<DD + 1, DD>>>(w2_2, w2_out, b2_2);
    k_mlp<<<(NN + 63) / 64, 256>>>(eattr, w2_1, b2_1);
    k_gather<<<(NN * 32 + 255) / 256, 256>>>(b2_out, out);
}

// round 7
// speedup vs baseline: 1.9223x; 1.4306x over previous
#include <cuda_runtime.h>
#include <mma.h>
#include <cstdint>

using namespace nvcuda;

#define NN 50000
#define EE 800000
#define DD 128
#define SCAN_G ((NN + 255) / 256)   // 196 blocks
#define MLP_G  ((NN + 127) / 128)   // 391 CTAs
#define LDS_W  (DD + 4)             // 132 floats, padded

// ---------------- device-global scratch (no allocations allowed) ------------
__device__ float d_g[NN * DD];
__device__ float d_Wc[DD * DD];     // folded W2 @ Wout (fp32)
__device__ float d_bc[DD];          // folded b2 @ Wout
__device__ int   d_deg[NN];
__device__ int   d_offs[NN + 1];
__device__ int   d_cursor[NN];
__device__ int   d_csr[EE];
__device__ int   d_is64;
__device__ int   d_bsum[SCAN_G];
__device__ int   d_boff[SCAN_G];

__device__ __forceinline__ float f2tf(float x) {
    uint32_t u;
    asm("cvt.rna.tf32.f32 %0, %1;" : "=r"(u) : "f"(x));
    return __uint_as_float(u);
}

// ---------------- edge_index dtype handling --------------------------------
// JAX may emit int32 (x64 disabled, default) or int64. For int64 LE values
// < 2^31 every odd int32 word is zero; 16 consecutive zero odd words from
// genuine int32 ids is ~impossible.
__global__ void k_detect(const int* __restrict__ ei32) {
    if (threadIdx.x == 0) {
        int s = 0;
        #pragma unroll
        for (int i = 0; i < 16; i++) s |= ei32[2 * i + 1];
        d_is64 = (s == 0) ? 1 : 0;
    }
}
__device__ __forceinline__ int edge_at(const void* ei, int is64, int idx) {
    if (is64) return (int)((const long long*)ei)[idx];
    return ((const int*)ei)[idx];
}

// ---------------- CSR build --------------------------------------------------
__global__ void k_zero_deg() {
    int i = blockIdx.x * blockDim.x + threadIdx.x;
    if (i < NN) d_deg[i] = 0;
}
__global__ void k_count(const void* __restrict__ ei) {
    int i = blockIdx.x * blockDim.x + threadIdx.x;
    if (i < EE) {
        int is64 = d_is64;
        atomicAdd(&d_deg[edge_at(ei, is64, EE + i)], 1);
    }
}
__global__ __launch_bounds__(256) void k_scan_blk() {
    __shared__ int ws[8];
    int tid = threadIdx.x;
    int i = blockIdx.x * 256 + tid;
    int lane = tid & 31, wid = tid >> 5;
    int v = (i < NN) ? d_deg[i] : 0;
    int inc = v;
    #pragma unroll
    for (int o = 1; o < 32; o <<= 1) {
        int t = __shfl_up_sync(0xffffffffu, inc, o);
        if (lane >= o) inc += t;
    }
    if (lane == 31) ws[wid] = inc;
    __syncthreads();
    if (wid == 0 && lane < 8) {
        int t = ws[lane];
        #pragma unroll
        for (int o = 1; o < 8; o <<= 1) {
            int u = __shfl_up_sync(0x000000ffu, t, o);
            if (lane >= o) t += u;
        }
        ws[lane] = t;
    }
    __syncthreads();
    int excl = inc - v + (wid ? ws[wid - 1] : 0);
    if (i < NN) d_offs[i] = excl;
    if (tid == 255) d_bsum[blockIdx.x] = ws[7];
}
__global__ __launch_bounds__(256) void k_scan_top() {
    __shared__ int ws[8];
    int tid = threadIdx.x;
    int lane = tid & 31, wid = tid >> 5;
    int v = (tid < SCAN_G) ? d_bsum[tid] : 0;
    int inc = v;
    #pragma unroll
    for (int o = 1; o < 32; o <<= 1) {
        int t = __shfl_up_sync(0xffffffffu, inc, o);
        if (lane >= o) inc += t;
    }
    if (lane == 31) ws[wid] = inc;
    __syncthreads();
    if (wid == 0 && lane < 8) {
        int t = ws[lane];
        #pragma unroll
        for (int o = 1; o < 8; o <<= 1) {
            int u = __shfl_up_sync(0x000000ffu, t, o);
            if (lane >= o) t += u;
        }
        ws[lane] = t;
    }
    __syncthreads();
    int excl = inc - v + (wid ? ws[wid - 1] : 0);
    if (tid < SCAN_G) d_boff[tid] = excl;
    if (tid == 255) d_offs[NN] = ws[7];
}
__global__ __launch_bounds__(256) void k_scan_add() {
    int i = blockIdx.x * 256 + threadIdx.x;
    if (i < NN) {
        int o = d_offs[i] + d_boff[blockIdx.x];
        d_offs[i] = o;
        d_cursor[i] = o;
    }
}
__global__ void k_fill(const void* __restrict__ ei) {
    int i = blockIdx.x * blockDim.x + threadIdx.x;
    if (i < EE) {
        int is64 = d_is64;
        int src = edge_at(ei, is64, i);
        int dst = edge_at(ei, is64, EE + i);
        d_csr[atomicAdd(&d_cursor[dst], 1)] = src;
    }
}

// ---------------- weight folding --------------------------------------------
__global__ void k_pre(const float* __restrict__ w2, const float* __restrict__ wo,
                      const float* __restrict__ b2) {
    int j = threadIdx.x;
    if (blockIdx.x < DD) {
        int i = blockIdx.x;
        float acc = 0.f;
        #pragma unroll 8
        for (int k = 0; k < DD; k++) acc += w2[i * DD + k] * wo[k * DD + j];
        d_Wc[i * DD + j] = acc;
    } else {
        float acc = 0.f;
        #pragma unroll 8
        for (int k = 0; k < DD; k++) acc += b2[k] * wo[k * DD + j];
        d_bc[j] = acc;
    }
}

// ---------------- wmma tf32 fused 2-GEMM MLP --------------------------------
// d_g[m0..m0+127] = relu(X@W1 + b1) @ Wc + bc
// 8 warps: warp_m = wid&3 (32 rows), warp_n = wid>>2 (64 cols)
__global__ __launch_bounds__(256) void k_mlp_tc(const float* __restrict__ X,
                                                const float* __restrict__ w1,
                                                const float* __restrict__ b1) {
    extern __shared__ float sm[];
    float* sA  = sm;                       // [128][132] A tile (tf32-in-float)
    float* sB1 = sm + 128 * LDS_W;         // [128][132] W1 tile / staging
    float* sB2 = sm + 2 * 128 * LDS_W;     // [128][132] Wc tile

    int tid = threadIdx.x;
    int wid = tid >> 5;
    int m0 = blockIdx.x * 128;
    int wm = (wid & 3) * 32;               // warp row base
    int wn = (wid >> 2) * 64;              // warp col base

    // load A (X rows, tf32-convert, zero-pad OOB) and both weight tiles
    #pragma unroll
    for (int i = 0; i < 16; i++) {
        int g = tid + 256 * i;             // float4 group 0..4095
        int r = g >> 5;
        int c = (g & 31) << 2;
        float4 v = make_float4(0.f, 0.f, 0.f, 0.f);
        if (m0 + r < NN)
            v = *reinterpret_cast<const float4*>(&X[(size_t)(m0 + r) * DD + c]);
        float* p = &sA[r * LDS_W + c];
        p[0] = f2tf(v.x); p[1] = f2tf(v.y); p[2] = f2tf(v.z); p[3] = f2tf(v.w);

        float4 wv = *reinterpret_cast<const float4*>(&w1[r * DD + c]);
        float* q = &sB1[r * LDS_W + c];
        q[0] = f2tf(wv.x); q[1] = f2tf(wv.y); q[2] = f2tf(wv.z); q[3] = f2tf(wv.w);

        float4 cv = *reinterpret_cast<const float4*>(&d_Wc[r * DD + c]);
        float* s = &sB2[r * LDS_W + c];
        s[0] = f2tf(cv.x); s[1] = f2tf(cv.y); s[2] = f2tf(cv.z); s[3] = f2tf(cv.w);
    }
    __syncthreads();

    // ---- GEMM1: D1 = A @ W1 ----
    wmma::fragment<wmma::accumulator, 16, 16, 8, float> c1[2][4];
    #pragma unroll
    for (int i = 0; i < 2; i++)
        #pragma unroll
        for (int j = 0; j < 4; j++) wmma::fill_fragment(c1[i][j], 0.f);

    #pragma unroll
    for (int k = 0; k < DD; k += 8) {
        wmma::fragment<wmma::matrix_a, 16, 16, 8, wmma::precision::tf32, wmma::row_major> a[2];
        wmma::fragment<wmma::matrix_b, 16, 16, 8, wmma::precision::tf32, wmma::row_major> b[4];
        #pragma unroll
        for (int i = 0; i < 2; i++)
            wmma::load_matrix_sync(a[i], &sA[(wm + i * 16) * LDS_W + k], LDS_W);
        #pragma unroll
        for (int j = 0; j < 4; j++)
            wmma::load_matrix_sync(b[j], &sB1[k * LDS_W + wn + j * 16], LDS_W);
        #pragma unroll
        for (int i = 0; i < 2; i++)
            #pragma unroll
            for (int j = 0; j < 4; j++)
                wmma::mma_sync(c1[i][j], a[i], b[j], c1[i][j]);
    }
    __syncthreads();   // everyone done reading sA/sB1

    // epilogue 1: stage D1 into sB1, then relu(+b1) -> tf32 -> sA
    #pragma unroll
    for (int i = 0; i < 2; i++)
        #pragma unroll
        for (int j = 0; j < 4; j++)
            wmma::store_matrix_sync(&sB1[(wm + i * 16) * LDS_W + wn + j * 16],
                                    c1[i][j], LDS_W, wmma::mem_row_major);
    __syncthreads();
    for (int i = tid; i < 128 * DD; i += 256) {
        int r = i >> 7, c = i & 127;
        float v = sB1[r * LDS_W + c] + __ldg(&b1[c]);
        sA[r * LDS_W + c] = f2tf(v > 0.f ? v : 0.f);
    }
    __syncthreads();

    // ---- GEMM2: D2 = A' @ Wc ----
    wmma::fragment<wmma::accumulator, 16, 16, 8, float> c2[2][4];
    #pragma unroll
    for (int i = 0; i < 2; i++)
        #pragma unroll
        for (int j = 0; j < 4; j++) wmma::fill_fragment(c2[i][j], 0.f);

    #pragma unroll
    for (int k = 0; k < DD; k += 8) {
        wmma::fragment<wmma::matrix_a, 16, 16, 8, wmma::precision::tf32, wmma::row_major> a[2];
        wmma::fragment<wmma::matrix_b, 16, 16, 8, wmma::precision::tf32, wmma::row_major> b[4];
        #pragma unroll
        for (int i = 0; i < 2; i++)
            wmma::load_matrix_sync(a[i], &sA[(wm + i * 16) * LDS_W + k], LDS_W);
        #pragma unroll
        for (int j = 0; j < 4; j++)
            wmma::load_matrix_sync(b[j], &sB2[k * LDS_W + wn + j * 16], LDS_W);
        #pragma unroll
        for (int i = 0; i < 2; i++)
            #pragma unroll
            for (int j = 0; j < 4; j++)
                wmma::mma_sync(c2[i][j], a[i], b[j], c2[i][j]);
    }
    __syncthreads();

    // epilogue 2: stage D2 into sB1, add bc, write to d_g (float4)
    #pragma unroll
    for (int i = 0; i < 2; i++)
        #pragma unroll
        for (int j = 0; j < 4; j++)
            wmma::store_matrix_sync(&sB1[(wm + i * 16) * LDS_W + wn + j * 16],
                                    c2[i][j], LDS_W, wmma::mem_row_major);
    __syncthreads();
    #pragma unroll
    for (int i = 0; i < 16; i++) {
        int g = tid + 256 * i;             // float4 group
        int r = g >> 5;
        int c = (g & 31) << 2;
        if (m0 + r < NN) {
            const float* p = &sB1[r * LDS_W + c];
            float4 o;
            o.x = p[0] + d_bc[c + 0];
            o.y = p[1] + d_bc[c + 1];
            o.z = p[2] + d_bc[c + 2];
            o.w = p[3] + d_bc[c + 3];
            *reinterpret_cast<float4*>(&d_g[(size_t)(m0 + r) * DD + c]) = o;
        }
    }
}

// ---------------- per-node gather + mean + bias -----------------------------
__global__ __launch_bounds__(256) void k_gather(const float* __restrict__ bo,
                                                float* __restrict__ out) {
    int gtid = blockIdx.x * blockDim.x + threadIdx.x;
    int node = gtid >> 5;
    int lane = gtid & 31;
    if (node >= NN) return;

    const float4* g4 = reinterpret_cast<const float4*>(d_g);
    float4 acc = g4[(size_t)node * 32 + lane];   // self-loop

    int start = d_offs[node];
    int end   = d_offs[node + 1];

    for (int j = start; j < end; j += 32) {
        int v = (j + lane < end) ? d_csr[j + lane] : 0;
        int cnt = end - j; if (cnt > 32) cnt = 32;
        for (int i = 0; i < cnt; i++) {
            int s = __shfl_sync(0xffffffffu, v, i);
            float4 t = g4[(size_t)s * 32 + lane];
            acc.x += t.x; acc.y += t.y; acc.z += t.z; acc.w += t.w;
        }
    }

    float inv = 1.0f / (float)(end - start + 1);
    float4 bb = reinterpret_cast<const float4*>(bo)[lane];
    float4 o = make_float4(acc.x * inv + bb.x, acc.y * inv + bb.y,
                           acc.z * inv + bb.z, acc.w * inv + bb.w);
    reinterpret_cast<float4*>(out)[(size_t)node * 32 + lane] = o;
}

// ---------------- launch ----------------------------------------------------
#define SMEM_MLP (3 * 128 * LDS_W * 4)   // 202752 bytes

extern "C" void kernel_launch(void* const* d_in, const int* in_sizes, int n_in,
                              void* d_out, int out_size) {
    const void* ei       = d_in[0];
    const float* eattr   = (const float*)d_in[1];
    const float* w2_1    = (const float*)d_in[8];
    const float* b2_1    = (const float*)d_in[9];
    const float* w2_2    = (const float*)d_in[10];
    const float* b2_2    = (const float*)d_in[11];
    const float* w2_out  = (const float*)d_in[12];
    const float* b2_out  = (const float*)d_in[13];
    float* out = (float*)d_out;

    cudaFuncSetAttribute(k_mlp_tc, cudaFuncAttributeMaxDynamicSharedMemorySize, SMEM_MLP);

    // launch index 3 (the one ncu captures) = k_mlp_tc
    k_detect<<<1, 32>>>((const int*)ei);                          // 0
    k_pre<<<DD + 1, DD>>>(w2_2, w2_out, b2_2);                    // 1
    k_zero_deg<<<(NN + 255) / 256, 256>>>();                      // 2
    k_mlp_tc<<<MLP_G, 256, SMEM_MLP>>>(eattr, w2_1, b2_1);        // 3  <- profiled
    k_count<<<(EE + 255) / 256, 256>>>(ei);                       // 4
    k_scan_blk<<<SCAN_G, 256>>>();                                // 5
    k_scan_top<<<1, 256>>>();                                     // 6
    k_scan_add<<<SCAN_G, 256>>>();                                // 7
    k_fill<<<(EE + 255) / 256, 256>>>(ei);                        // 8
    k_gather<<<(NN * 32 + 255) / 256, 256>>>(b2_out, out);        // 9
}